// round 11
// baseline (speedup 1.0000x reference)
#include <cuda_runtime.h>
#include <cuda_bf16.h>
#include <cstdint>

#define DD    16
#define HH    64
#define WW    64
#define PTOT  (DD*HH*WW)      // 65536
#define C3    21
#define LOG2E 1.4426950408889634f

// scratch: rows 0-63 = q, 64-127 = k, 128-191 = v
__device__ float g_qkv[192 * PTOT];
// x split hi/lo, transposed to [pos][ci] bf16 (128B rows)
__device__ __align__(16) __nv_bfloat16 g_xhi[PTOT * 64];
__device__ __align__(16) __nv_bfloat16 g_xlo[PTOT * 64];
// W split hi/lo, [c][ci] bf16 (192 rows x 64)
__device__ __align__(16) __nv_bfloat16 g_whi[192 * 64];
__device__ __align__(16) __nv_bfloat16 g_wlo[192 * 64];

__device__ __forceinline__ float ex2(float x) {
    float r;
    asm("ex2.approx.ftz.f32 %0, %1;" : "=f"(r) : "f"(x));
    return r;
}
__device__ __forceinline__ void cpasync16(unsigned int dst, const void* src) {
    asm volatile("cp.async.cg.shared.global [%0], [%1], 16;\n" :: "r"(dst), "l"(src));
}
__device__ __forceinline__ void cp_commit() {
    asm volatile("cp.async.commit_group;\n" ::: "memory");
}
__device__ __forceinline__ void cp_wait0() {
    asm volatile("cp.async.wait_group 0;\n" ::: "memory");
}

// ---------------------------------------------------------------------------
// Prep A: split x (fp32 [ci][pos]) into bf16 hi/lo in transposed [pos][ci].
// ---------------------------------------------------------------------------
__global__ void __launch_bounds__(256)
prep_x_kernel(const float* __restrict__ x) {
    __shared__ float tile[64 * 65];
    const int tid = threadIdx.x;
    const int p0  = blockIdx.x * 64;

#pragma unroll
    for (int i = 0; i < 16; i++) {
        int j  = i * 256 + tid;
        int ci = j >> 6, p = j & 63;
        tile[ci * 65 + p] = x[ci * PTOT + p0 + p];
    }
    __syncthreads();
#pragma unroll
    for (int i = 0; i < 16; i++) {
        int j  = i * 256 + tid;
        int p  = j >> 6, ci = j & 63;
        float v = tile[ci * 65 + p];
        __nv_bfloat16 hi = __float2bfloat16(v);
        __nv_bfloat16 lo = __float2bfloat16(v - __bfloat162float(hi));
        g_xhi[(p0 + p) * 64 + ci] = hi;
        g_xlo[(p0 + p) * 64 + ci] = lo;
    }
}

// ---------------------------------------------------------------------------
// Prep B: split W into bf16 hi/lo.
// ---------------------------------------------------------------------------
__global__ void prep_w_kernel(const float* __restrict__ wq,
                              const float* __restrict__ wk,
                              const float* __restrict__ wv) {
    int j = blockIdx.x * 256 + threadIdx.x;
    if (j < 192 * 64) {
        int c = j >> 6, ci = j & 63;
        float w;
        if (c < 64)       w = wq[c * 64 + ci];
        else if (c < 128) w = wk[(c - 64) * 64 + ci];
        else              w = wv[(c - 128) * 64 + ci];
        __nv_bfloat16 hi = __float2bfloat16(w);
        __nv_bfloat16 lo = __float2bfloat16(w - __bfloat162float(hi));
        g_whi[j] = hi;
        g_wlo[j] = lo;
    }
}

// ---------------------------------------------------------------------------
// Kernel 1: qkv GEMM, cp.async -> swizzled smem -> ldmatrix -> mma.sync.
// Block: 256 thr (2 pos-warps x 4 chan-warps), tile 64 pos x 192 chan.
// smem: A hi/lo 8KB each (64 rows x 128B), B hi/lo 24KB each (192 x 128B),
// XOR swizzle chunk^=(row&7) -> ldmatrix conflict-free.
// Epilogue via smem transpose (stride 68) -> fully coalesced STG.128.
// ---------------------------------------------------------------------------
#define SM_AHI  0
#define SM_ALO  8192
#define SM_BHI  16384
#define SM_BLO  40960
#define SM_TOT  65536

__device__ __forceinline__ void ldmx4(unsigned int& r0, unsigned int& r1,
                                      unsigned int& r2, unsigned int& r3,
                                      unsigned int addr) {
    asm volatile("ldmatrix.sync.aligned.m8n8.x4.shared.b16 {%0,%1,%2,%3}, [%4];"
                 : "=r"(r0), "=r"(r1), "=r"(r2), "=r"(r3) : "r"(addr));
}

__device__ __forceinline__ void mma16816(float* d,
                                         unsigned int a0, unsigned int a1,
                                         unsigned int a2, unsigned int a3,
                                         unsigned int b0, unsigned int b1) {
    asm volatile(
        "mma.sync.aligned.m16n8k16.row.col.f32.bf16.bf16.f32 "
        "{%0,%1,%2,%3}, {%4,%5,%6,%7}, {%8,%9}, {%0,%1,%2,%3};"
        : "+f"(d[0]), "+f"(d[1]), "+f"(d[2]), "+f"(d[3])
        : "r"(a0), "r"(a1), "r"(a2), "r"(a3), "r"(b0), "r"(b1));
}

__global__ void __launch_bounds__(256, 2)
qkv_mma_kernel() {
    extern __shared__ char smem[];
    const unsigned int sb = (unsigned int)__cvta_generic_to_shared(smem);
    const int tid  = threadIdx.x;
    const int lane = tid & 31;
    const int wid  = tid >> 5;
    const int pw   = wid & 1;
    const int cw   = wid >> 1;
    const int p0   = blockIdx.x * 64;

    // ---- stage A (x hi/lo, 64 rows) and B (W hi/lo, 192 rows), swizzled ----
    {
        // A: 512 chunks each buf, 2 iters
#pragma unroll
        for (int i = 0; i < 2; i++) {
            int j   = i * 256 + tid;
            int row = j >> 3, c = j & 7;
            unsigned int dst = row * 128 + ((c ^ (row & 7)) << 4);
            const char* srh = (const char*)g_xhi + (size_t)(p0 + row) * 128 + c * 16;
            const char* srl = (const char*)g_xlo + (size_t)(p0 + row) * 128 + c * 16;
            cpasync16(sb + SM_AHI + dst, srh);
            cpasync16(sb + SM_ALO + dst, srl);
        }
        // B: 1536 chunks each buf, 6 iters
#pragma unroll
        for (int i = 0; i < 6; i++) {
            int j   = i * 256 + tid;
            int row = j >> 3, c = j & 7;
            unsigned int dst = row * 128 + ((c ^ (row & 7)) << 4);
            cpasync16(sb + SM_BHI + dst, (const char*)g_whi + row * 128 + c * 16);
            cpasync16(sb + SM_BLO + dst, (const char*)g_wlo + row * 128 + c * 16);
        }
        cp_commit();
        cp_wait0();
    }
    __syncthreads();

    const int posw = pw * 32;          // warp's 32 positions (local)
    const int cb   = cw * 48;          // warp's 48 channels

    float acc[2][6][4];
#pragma unroll
    for (int m = 0; m < 2; m++)
#pragma unroll
        for (int n = 0; n < 6; n++)
#pragma unroll
            for (int i = 0; i < 4; i++) acc[m][n][i] = 0.f;

    const int lrow = lane & 15;
    const int lcol = lane >> 4;

#pragma unroll
    for (int k = 0; k < 4; k++) {
        const int cc = k * 2 + lcol;   // logical 16B chunk

        // B fragments: 3 x4-loads per buf cover 48 chans (2 n-tiles each)
        unsigned int bh0[6], bh1[6], bl0[6], bl1[6];
#pragma unroll
        for (int t = 0; t < 3; t++) {
            int row = cb + t * 16 + lrow;
            unsigned int ad = row * 128 + ((cc ^ (row & 7)) << 4);
            ldmx4(bh0[2*t], bh0[2*t+1], bh1[2*t], bh1[2*t+1], sb + SM_BHI + ad);
            ldmx4(bl0[2*t], bl0[2*t+1], bl1[2*t], bl1[2*t+1], sb + SM_BLO + ad);
        }
#pragma unroll
        for (int m = 0; m < 2; m++) {
            int row = posw + m * 16 + lrow;
            unsigned int ad = row * 128 + ((cc ^ (row & 7)) << 4);
            unsigned int ah0, ah1, ah2, ah3, al0, al1, al2, al3;
            ldmx4(ah0, ah1, ah2, ah3, sb + SM_AHI + ad);
            ldmx4(al0, al1, al2, al3, sb + SM_ALO + ad);
#pragma unroll
            for (int n = 0; n < 6; n++) {
                mma16816(acc[m][n], ah0, ah1, ah2, ah3, bh0[n], bh1[n]);
                mma16816(acc[m][n], al0, al1, al2, al3, bh0[n], bh1[n]);
                mma16816(acc[m][n], ah0, ah1, ah2, ah3, bl0[n], bl1[n]);
            }
        }
    }

    // ---- epilogue: smem transpose (stride 68 -> bank-disjoint STS), then
    //      coalesced float4 stores ----
    __syncthreads();                        // done reading A/B smem
    float* sout = (float*)smem;             // 192 x 68 floats = 52224 B
    const int r  = lane >> 2;
    const int c2 = (lane & 3) * 2;
#pragma unroll
    for (int m = 0; m < 2; m++)
#pragma unroll
        for (int n = 0; n < 6; n++) {
            int chan = cb + n * 8 + c2;
            int pl   = posw + m * 16 + r;
            sout[chan * 68 + pl]            = acc[m][n][0];
            sout[(chan + 1) * 68 + pl]      = acc[m][n][1];
            sout[chan * 68 + pl + 8]        = acc[m][n][2];
            sout[(chan + 1) * 68 + pl + 8]  = acc[m][n][3];
        }
    __syncthreads();

#pragma unroll
    for (int it = 0; it < 12; it++) {
        int j    = it * 256 + tid;
        int chan = j >> 4;
        int f4   = j & 15;
        float4 v = *(const float4*)(sout + chan * 68 + f4 * 4);
        *(float4*)(g_qkv + (size_t)chan * PTOT + p0 + f4 * 4) = v;
    }
}

// ---------------------------------------------------------------------------
// Kernel 2: windowed softmax attention, TH=2 (unchanged from round 10).
// ---------------------------------------------------------------------------
#define RL 66

template<int A>
__device__ __forceinline__ void tap_loop(const float2* __restrict__ skv,
                                         int hb, int w,
                                         float qs0, float qs1,
                                         const float* qb0, const float* qb1,
                                         float& den0, float& num0,
                                         float& den1, float& num1) {
#pragma unroll
    for (int kd = 0; kd < 3; kd++) {
#pragma unroll
        for (int R = 0; R < 4; R++) {
            const float2* row = skv + (kd * 18 + hb + R) * RL + w;
#pragma unroll
            for (int kw = 0; kw < 3; kw++) {
                float2 kv = row[kw];
                if (R <= 2) {
                    const int j = (A == 0) ? kd : (A == 1) ? R : kw;
                    float e = ex2(fmaf(qs0, kv.x, qb0[j]));
                    den0 += e;
                    num0 = fmaf(e, kv.y, num0);
                }
                if (R >= 1) {
                    const int j = (A == 0) ? kd : (A == 1) ? (R - 1) : kw;
                    float e = ex2(fmaf(qs1, kv.x, qb1[j]));
                    den1 += e;
                    num1 = fmaf(e, kv.y, num1);
                }
            }
        }
    }
}

__global__ void __launch_bounds__(512)
attn_kernel(const float* __restrict__ rel_d,
            const float* __restrict__ rel_h,
            const float* __restrict__ rel_w,
            float* __restrict__ out) {
    __shared__ float2 skv[3][18][RL];

    const int w   = threadIdx.x;
    const int ty  = threadIdx.y;
    const int tid = ty * 64 + w;
    const int d   = blockIdx.x >> 2;
    const int h0  = (blockIdx.x & 3) * 16;
    const int c   = blockIdx.y;

    const float* gk = g_qkv + (size_t)(64  + c) * PTOT;
    const float* gv = g_qkv + (size_t)(128 + c) * PTOT;

    if (tid < 108) {
        int row = tid >> 1;
        int col = (tid & 1) * 65;
        (&skv[0][0][0])[row * RL + col] = make_float2(0.f, 0.f);
    }
    for (int idx = tid; idx < 54 * 64; idx += 512) {
        int row = idx >> 6;
        int col = idx & 63;
        int kd  = row / 18;
        int R   = row - kd * 18;
        int nd  = d + kd - 1;
        int nh  = h0 + R - 1;
        float kk = 0.f, vv = 0.f;
        if ((unsigned)nd < (unsigned)DD && (unsigned)nh < (unsigned)HH) {
            int g = (nd << 12) + (nh << 6) + col;
            kk = gk[g];
            vv = gv[g];
        }
        skv[kd][R][col + 1] = make_float2(kk, vv);
    }
    __syncthreads();

    const int hb = ty * 2;
    const int p0 = (d << 12) + ((h0 + hb) << 6) + w;
    const float qs0 = g_qkv[(size_t)c * PTOT + p0] * LOG2E;
    const float qs1 = g_qkv[(size_t)c * PTOT + p0 + 64] * LOG2E;

    int axis;
    const float* bp;
    if (c < C3)          { axis = 0; bp = rel_d + c * 3; }
    else if (c < 2 * C3) { axis = 1; bp = rel_h + (c - C3) * 3; }
    else                 { axis = 2; bp = rel_w + (c - 2 * C3) * 3; }
    float qb0[3], qb1[3];
#pragma unroll
    for (int j = 0; j < 3; j++) {
        float b = bp[j];
        qb0[j] = qs0 * b;
        qb1[j] = qs1 * b;
    }

    float den0 = 0.f, num0 = 0.f, den1 = 0.f, num1 = 0.f;
    const float2* base = &skv[0][0][0];
    if (axis == 0)      tap_loop<0>(base, hb, w, qs0, qs1, qb0, qb1, den0, num0, den1, num1);
    else if (axis == 1) tap_loop<1>(base, hb, w, qs0, qs1, qb0, qb1, den0, num0, den1, num1);
    else                tap_loop<2>(base, hb, w, qs0, qs1, qb0, qb1, den0, num0, den1, num1);

    out[(size_t)c * PTOT + p0]      = __fdividef(num0, den0);
    out[(size_t)c * PTOT + p0 + 64] = __fdividef(num1, den1);
}

// ---------------------------------------------------------------------------
extern "C" void kernel_launch(void* const* d_in, const int* in_sizes, int n_in,
                              void* d_out, int out_size) {
    const float* x     = (const float*)d_in[0];
    const float* wq    = (const float*)d_in[1];
    const float* wk    = (const float*)d_in[2];
    const float* wv    = (const float*)d_in[3];
    const float* rel_d = (const float*)d_in[4];
    const float* rel_h = (const float*)d_in[5];
    const float* rel_w = (const float*)d_in[6];
    float* out = (float*)d_out;

    prep_w_kernel<<<48, 256>>>(wq, wk, wv);
    prep_x_kernel<<<PTOT / 64, 256>>>(x);

    cudaFuncSetAttribute(qkv_mma_kernel,
                         cudaFuncAttributeMaxDynamicSharedMemorySize, SM_TOT);
    qkv_mma_kernel<<<PTOT / 64, 256, SM_TOT>>>();

    dim3 agrid(DD * (HH / 16), 64);
    dim3 ablock(WW, 8);
    attn_kernel<<<agrid, ablock>>>(rel_d, rel_h, rel_w, out);
}

// round 13
// speedup vs baseline: 1.6134x; 1.6134x over previous
#include <cuda_runtime.h>
#include <cuda_bf16.h>
#include <cstdint>

#define DD    16
#define HH    64
#define WW    64
#define PTOT  (DD*HH*WW)      // 65536
#define C3    21
#define LOG2E 1.4426950408889634f

// scratch: rows 0-63 = q, 64-127 = k, 128-191 = v
__device__ float g_qkv[192 * PTOT];

// fragment-major operands for m16n8k16 row.col:
//  A: per (16-pos tile, k-step): 32 lanes x uint4 {a0,a1,a2,a3}
//  B: per (8-chan tile,  k-step): 32 lanes x uint2 {b0,b1}
__device__ __align__(16) uint4 g_xhf[(PTOT / 16) * 4 * 32];
__device__ __align__(16) uint4 g_xlf[(PTOT / 16) * 4 * 32];
__device__ __align__(16) uint2 g_whf[24 * 4 * 32];
__device__ __align__(16) uint2 g_wlf[24 * 4 * 32];

__device__ __forceinline__ float ex2(float x) {
    float r;
    asm("ex2.approx.ftz.f32 %0, %1;" : "=f"(r) : "f"(x));
    return r;
}

__device__ __forceinline__ unsigned int packbf(float a, float b) {
    __nv_bfloat162 h = __floats2bfloat162_rn(a, b);
    return *(unsigned int*)&h;
}

// ---------------------------------------------------------------------------
// Prep A: x (fp32 [ci][pos]) -> fragment-major bf16 hi/lo.
// Per block: 64 positions (4 pos-tiles). Transpose through smem, then write
// 512 uint4 per buffer, lane-linear (fully coalesced).
// word0 = X[r][kc..+1], word1 = X[r+8][kc..], word2 = X[r][kc+8..], word3 = X[r+8][kc+8..]
// (r = lane>>2, kc = k*16 + (lane&3)*2)
// ---------------------------------------------------------------------------
__global__ void __launch_bounds__(256)
prep_x_kernel(const float* __restrict__ x) {
    __shared__ float tile[64 * 65];       // [ci][p]
    const int tid = threadIdx.x;
    const int p0  = blockIdx.x * 64;

#pragma unroll
    for (int i = 0; i < 16; i++) {
        int j  = i * 256 + tid;
        int ci = j >> 6, p = j & 63;
        tile[ci * 65 + p] = x[ci * PTOT + p0 + p];
    }
    __syncthreads();

#pragma unroll
    for (int i = 0; i < 2; i++) {
        int j    = i * 256 + tid;         // 0..511
        int lane = j & 31;
        int k    = (j >> 5) & 3;
        int lt   = j >> 7;                // local pos-tile 0..3
        int r    = lane >> 2;
        int kc   = k * 16 + (lane & 3) * 2;
        int pa   = lt * 16 + r;           // local pos of rows r / r+8
        int pb   = pa + 8;

        float v00 = tile[kc * 65 + pa],       v01 = tile[(kc + 1) * 65 + pa];
        float v10 = tile[kc * 65 + pb],       v11 = tile[(kc + 1) * 65 + pb];
        float v20 = tile[(kc + 8) * 65 + pa], v21 = tile[(kc + 9) * 65 + pa];
        float v30 = tile[(kc + 8) * 65 + pb], v31 = tile[(kc + 9) * 65 + pb];

        float h00 = __bfloat162float(__float2bfloat16(v00));
        float h01 = __bfloat162float(__float2bfloat16(v01));
        float h10 = __bfloat162float(__float2bfloat16(v10));
        float h11 = __bfloat162float(__float2bfloat16(v11));
        float h20 = __bfloat162float(__float2bfloat16(v20));
        float h21 = __bfloat162float(__float2bfloat16(v21));
        float h30 = __bfloat162float(__float2bfloat16(v30));
        float h31 = __bfloat162float(__float2bfloat16(v31));

        size_t idx = ((size_t)(p0 / 16 + lt) * 4 + k) * 32 + lane;
        g_xhf[idx] = make_uint4(packbf(h00, h01), packbf(h10, h11),
                                packbf(h20, h21), packbf(h30, h31));
        g_xlf[idx] = make_uint4(packbf(v00 - h00, v01 - h01),
                                packbf(v10 - h10, v11 - h11),
                                packbf(v20 - h20, v21 - h21),
                                packbf(v30 - h30, v31 - h31));
    }
}

// ---------------------------------------------------------------------------
// Prep B: W -> fragment-major bf16 hi/lo. chan = ntile*8 + (lane>>2),
// b0 = W[chan][kc..+1], b1 = W[chan][kc+8..+9].
// ---------------------------------------------------------------------------
__global__ void prep_w_kernel(const float* __restrict__ wq,
                              const float* __restrict__ wk,
                              const float* __restrict__ wv) {
    int j = blockIdx.x * 256 + threadIdx.x;   // 0..3071
    if (j >= 24 * 4 * 32) return;
    int lane = j & 31;
    int k    = (j >> 5) & 3;
    int nt   = j >> 7;                        // 0..23
    int c    = nt * 8 + (lane >> 2);
    int kc   = k * 16 + (lane & 3) * 2;

    const float* src;
    int cr = c;
    if (c < 64)       { src = wq; }
    else if (c < 128) { src = wk; cr = c - 64; }
    else              { src = wv; cr = c - 128; }

    float v00 = src[cr * 64 + kc],     v01 = src[cr * 64 + kc + 1];
    float v10 = src[cr * 64 + kc + 8], v11 = src[cr * 64 + kc + 9];

    float h00 = __bfloat162float(__float2bfloat16(v00));
    float h01 = __bfloat162float(__float2bfloat16(v01));
    float h10 = __bfloat162float(__float2bfloat16(v10));
    float h11 = __bfloat162float(__float2bfloat16(v11));

    g_whf[j] = make_uint2(packbf(h00, h01), packbf(h10, h11));
    g_wlf[j] = make_uint2(packbf(v00 - h00, v01 - h01),
                          packbf(v10 - h10, v11 - h11));
}

// ---------------------------------------------------------------------------
// Kernel 1: qkv GEMM, coalesced fragment-major LDG -> mma.sync.
// Block 256 thr (2 pos-warps x 4 chan-warps), tile 64 pos x 192 chan.
// 3 fused passes: hi*hi + lo*hi + hi*lo. Epilogue: smem transpose (stride 68)
// then fully-coalesced float4 stores.
// ---------------------------------------------------------------------------
__device__ __forceinline__ void mma16816(float* d,
                                         unsigned int a0, unsigned int a1,
                                         unsigned int a2, unsigned int a3,
                                         unsigned int b0, unsigned int b1) {
    asm volatile(
        "mma.sync.aligned.m16n8k16.row.col.f32.bf16.bf16.f32 "
        "{%0,%1,%2,%3}, {%4,%5,%6,%7}, {%8,%9}, {%0,%1,%2,%3};"
        : "+f"(d[0]), "+f"(d[1]), "+f"(d[2]), "+f"(d[3])
        : "r"(a0), "r"(a1), "r"(a2), "r"(a3), "r"(b0), "r"(b1));
}

#define SM_QKV_TOT (192 * 68 * 4)   // 52224 B epilogue buffer

__global__ void __launch_bounds__(256, 2)
qkv_mma_kernel() {
    extern __shared__ char smem[];
    const int tid  = threadIdx.x;
    const int lane = tid & 31;
    const int wid  = tid >> 5;
    const int pw   = wid & 1;
    const int cw   = wid >> 1;
    const int p0   = blockIdx.x * 64;
    const int Tb   = blockIdx.x * 4;      // pos-tile base

    float acc[2][6][4];
#pragma unroll
    for (int m = 0; m < 2; m++)
#pragma unroll
        for (int n = 0; n < 6; n++)
#pragma unroll
            for (int i = 0; i < 4; i++) acc[m][n][i] = 0.f;

#pragma unroll
    for (int k = 0; k < 4; k++) {
        uint2 bh[6], bl[6];
#pragma unroll
        for (int n = 0; n < 6; n++) {
            int nt = cw * 6 + n;
            bh[n] = g_whf[(nt * 4 + k) * 32 + lane];
            bl[n] = g_wlf[(nt * 4 + k) * 32 + lane];
        }
#pragma unroll
        for (int m = 0; m < 2; m++) {
            size_t ai = ((size_t)(Tb + pw * 2 + m) * 4 + k) * 32 + lane;
            uint4 ah = g_xhf[ai];
            uint4 al = g_xlf[ai];
#pragma unroll
            for (int n = 0; n < 6; n++) {
                mma16816(acc[m][n], ah.x, ah.y, ah.z, ah.w, bh[n].x, bh[n].y);
                mma16816(acc[m][n], al.x, al.y, al.z, al.w, bh[n].x, bh[n].y);
                mma16816(acc[m][n], ah.x, ah.y, ah.z, ah.w, bl[n].x, bl[n].y);
            }
        }
    }

    // epilogue: smem transpose (stride 68), then coalesced float4 stores
    float* sout = (float*)smem;
    const int posw = pw * 32;
    const int cb   = cw * 48;
    const int r    = lane >> 2;
    const int c2   = (lane & 3) * 2;
#pragma unroll
    for (int m = 0; m < 2; m++)
#pragma unroll
        for (int n = 0; n < 6; n++) {
            int chan = cb + n * 8 + c2;
            int pl   = posw + m * 16 + r;
            sout[chan * 68 + pl]           = acc[m][n][0];
            sout[(chan + 1) * 68 + pl]     = acc[m][n][1];
            sout[chan * 68 + pl + 8]       = acc[m][n][2];
            sout[(chan + 1) * 68 + pl + 8] = acc[m][n][3];
        }
    __syncthreads();

#pragma unroll
    for (int it = 0; it < 12; it++) {
        int j    = it * 256 + tid;
        int chan = j >> 4;
        int f4   = j & 15;
        float4 v = *(const float4*)(sout + chan * 68 + f4 * 4);
        *(float4*)(g_qkv + (size_t)chan * PTOT + p0 + f4 * 4) = v;
    }
}

// ---------------------------------------------------------------------------
// Kernel 2: windowed softmax attention, TH=4 h-outputs per thread.
// Block (64 w, 4 ty): 1 channel, 16-h tile. Thread handles h = 4*ty .. +3,
// sharing tap loads over 6 smem rows (13.5 LDS.64 per output).
// ---------------------------------------------------------------------------
#define RL 66

template<int A>
__device__ __forceinline__ void tap_loop(const float2* __restrict__ skv,
                                         int hb, int w,
                                         const float* qs, const float (*qb)[3],
                                         float* den, float* num) {
#pragma unroll
    for (int kd = 0; kd < 3; kd++) {
#pragma unroll
        for (int R = 0; R < 6; R++) {
            const float2* row = skv + (kd * 18 + hb + R) * RL + w;
#pragma unroll
            for (int kw = 0; kw < 3; kw++) {
                float2 kv = row[kw];
#pragma unroll
                for (int o = 0; o < 4; o++) {
                    if (R >= o && R <= o + 2) {
                        const int j = (A == 0) ? kd : (A == 1) ? (R - o) : kw;
                        float e = ex2(fmaf(qs[o], kv.x, qb[o][j]));
                        den[o] += e;
                        num[o] = fmaf(e, kv.y, num[o]);
                    }
                }
            }
        }
    }
}

__global__ void __launch_bounds__(256)
attn_kernel(const float* __restrict__ rel_d,
            const float* __restrict__ rel_h,
            const float* __restrict__ rel_w,
            float* __restrict__ out) {
    __shared__ float2 skv[3][18][RL];

    const int w   = threadIdx.x;
    const int ty  = threadIdx.y;
    const int tid = ty * 64 + w;
    const int d   = blockIdx.x >> 2;
    const int h0  = (blockIdx.x & 3) * 16;
    const int c   = blockIdx.y;

    const float* gk = g_qkv + (size_t)(64  + c) * PTOT;
    const float* gv = g_qkv + (size_t)(128 + c) * PTOT;

    if (tid < 108) {
        int row = tid >> 1;
        int col = (tid & 1) * 65;
        (&skv[0][0][0])[row * RL + col] = make_float2(0.f, 0.f);
    }
    for (int idx = tid; idx < 54 * 64; idx += 256) {
        int row = idx >> 6;
        int col = idx & 63;
        int kd  = row / 18;
        int R   = row - kd * 18;
        int nd  = d + kd - 1;
        int nh  = h0 + R - 1;
        float kk = 0.f, vv = 0.f;
        if ((unsigned)nd < (unsigned)DD && (unsigned)nh < (unsigned)HH) {
            int g = (nd << 12) + (nh << 6) + col;
            kk = gk[g];
            vv = gv[g];
        }
        skv[kd][R][col + 1] = make_float2(kk, vv);
    }
    __syncthreads();

    const int hb = ty * 4;
    const int p0 = (d << 12) + ((h0 + hb) << 6) + w;

    float qs[4];
#pragma unroll
    for (int o = 0; o < 4; o++)
        qs[o] = g_qkv[(size_t)c * PTOT + p0 + o * 64] * LOG2E;

    int axis;
    const float* bp;
    if (c < C3)          { axis = 0; bp = rel_d + c * 3; }
    else if (c < 2 * C3) { axis = 1; bp = rel_h + (c - C3) * 3; }
    else                 { axis = 2; bp = rel_w + (c - 2 * C3) * 3; }
    float qb[4][3];
#pragma unroll
    for (int o = 0; o < 4; o++)
#pragma unroll
        for (int j = 0; j < 3; j++)
            qb[o][j] = qs[o] * bp[j];

    float den[4] = {0.f, 0.f, 0.f, 0.f};
    float num[4] = {0.f, 0.f, 0.f, 0.f};
    const float2* base = &skv[0][0][0];
    if (axis == 0)      tap_loop<0>(base, hb, w, qs, qb, den, num);
    else if (axis == 1) tap_loop<1>(base, hb, w, qs, qb, den, num);
    else                tap_loop<2>(base, hb, w, qs, qb, den, num);

#pragma unroll
    for (int o = 0; o < 4; o++)
        out[(size_t)c * PTOT + p0 + o * 64] = __fdividef(num[o], den[o]);
}

// ---------------------------------------------------------------------------
extern "C" void kernel_launch(void* const* d_in, const int* in_sizes, int n_in,
                              void* d_out, int out_size) {
    const float* x     = (const float*)d_in[0];
    const float* wq    = (const float*)d_in[1];
    const float* wk    = (const float*)d_in[2];
    const float* wv    = (const float*)d_in[3];
    const float* rel_d = (const float*)d_in[4];
    const float* rel_h = (const float*)d_in[5];
    const float* rel_w = (const float*)d_in[6];
    float* out = (float*)d_out;

    prep_w_kernel<<<12, 256>>>(wq, wk, wv);
    prep_x_kernel<<<PTOT / 64, 256>>>(x);

    cudaFuncSetAttribute(qkv_mma_kernel,
                         cudaFuncAttributeMaxDynamicSharedMemorySize, SM_QKV_TOT);
    qkv_mma_kernel<<<PTOT / 64, 256, SM_QKV_TOT>>>();

    dim3 agrid(DD * (HH / 16), 64);   // (64, 64)
    dim3 ablock(WW, 4);
    attn_kernel<<<agrid, ablock>>>(rel_d, rel_h, rel_w, out);
}